// round 1
// baseline (speedup 1.0000x reference)
#include <cuda_runtime.h>
#include <math.h>

#define IC 128      // memory capsules
#define NC 5        // classes
#define DD 153      // dim per capsule
#define CD 765      // NC*DD
#define KD 768      // input dim
#define NQV 256     // queries
#define EPSF 1e-8f

__device__ float g_hat_m[IC * CD];
__device__ float g_mc[IC * CD];      // centered hat_m (per (i,c) over d)
__device__ float g_norm_m[IC * NC];  // ||centered||
__device__ float g_hat_q[NQV * CD];

__device__ __forceinline__ float warp_sum(float v) {
#pragma unroll
  for (int o = 16; o; o >>= 1) v += __shfl_xor_sync(0xffffffffu, v, o);
  return v;
}

// ---------------------------------------------------------------------------
// GEMM: out[M,765] = A[M,768] @ W[768,765] + b
// block: 128 threads, tile 4 rows x 512 cols (thread: 4 interleaved cols)
// ---------------------------------------------------------------------------
__global__ __launch_bounds__(128) void gemm_kernel(
    const float* __restrict__ A, const float* __restrict__ W,
    const float* __restrict__ bias, float* __restrict__ out, int M) {
  __shared__ float As[4][KD];
  const int t = threadIdx.x;
  const int row0 = blockIdx.y * 4;
  const int c0 = blockIdx.x * 512;

  for (int idx = t; idx < 4 * KD; idx += 128) {
    int r = idx / KD, k = idx - r * KD;
    As[r][k] = (row0 + r < M) ? A[(row0 + r) * KD + k] : 0.f;
  }
  __syncthreads();

  float acc[4][4] = {};
  for (int k = 0; k < KD; ++k) {
    float a0 = As[0][k], a1 = As[1][k], a2 = As[2][k], a3 = As[3][k];
#pragma unroll
    for (int j = 0; j < 4; ++j) {
      int c = c0 + t + 128 * j;
      float w = (c < CD) ? W[k * CD + c] : 0.f;
      acc[0][j] += a0 * w;
      acc[1][j] += a1 * w;
      acc[2][j] += a2 * w;
      acc[3][j] += a3 * w;
    }
  }
#pragma unroll
  for (int j = 0; j < 4; ++j) {
    int c = c0 + t + 128 * j;
    if (c < CD) {
      float bb = bias[c];
#pragma unroll
      for (int r = 0; r < 4; ++r)
        if (row0 + r < M) out[(row0 + r) * CD + c] = acc[r][j] + bb;
    }
  }
}

// ---------------------------------------------------------------------------
// Stats: per (i,c): mean over d, centered copy, norm of centered.
// One warp per (i,c) group; layout [i][c][d] is contiguous -> group g owns
// hat_m[g*153 .. g*153+152].
// ---------------------------------------------------------------------------
__global__ __launch_bounds__(256) void stats_kernel(
    const float* __restrict__ hat_m, float* __restrict__ mc,
    float* __restrict__ norm_m) {
  int g = blockIdx.x * 8 + (threadIdx.x >> 5);
  int lane = threadIdx.x & 31;
  if (g >= IC * NC) return;
  const float* row = hat_m + g * DD;
  float s = 0.f;
  for (int d = lane; d < DD; d += 32) s += row[d];
  s = warp_sum(s);
  float mean = s * (1.f / DD);
  float s2 = 0.f;
  for (int d = lane; d < DD; d += 32) {
    float x = row[d] - mean;
    mc[g * DD + d] = x;
    s2 += x * x;
  }
  s2 = warp_sum(s2);
  if (lane == 0) norm_m[g] = sqrtf(s2);
}

// ---------------------------------------------------------------------------
// Routing: one block per query q. 256 threads = 8 warps.
// Per iteration:
//   norm_q[c] from tq (sum/sumsq; Pearson numerator needs no q-centering
//   because sum_d mc = 0)
//   fused pass over i: p[i,c] = tanh(dot(mc_ic, tq_c)/(nm*nq+eps));
//                      dsp = softmax_c(a[i,:]) + p; hat_v += hat_m_ic * dsp
//   v = squash(hat_v)
//   (if not final) m_dot_v pass, a += p*mdv, tq = (tq+v)/2
// Final iteration's v is the output row.
// ---------------------------------------------------------------------------
__global__ __launch_bounds__(256) void routing_kernel(
    const float* __restrict__ hat_m, const float* __restrict__ mc,
    const float* __restrict__ norm_m, const float* __restrict__ hat_q,
    float* __restrict__ out) {
  __shared__ float tq[CD];
  __shared__ float hv[CD];
  __shared__ float vv[CD];
  __shared__ float a_s[IC * NC];
  __shared__ float p_s[IC * NC];
  __shared__ float rnq[NC];

  const int q = blockIdx.x;
  const int t = threadIdx.x;
  const int warp = t >> 5, lane = t & 31;

  for (int j = t; j < CD; j += 256) tq[j] = hat_q[q * CD + j];
  for (int j = t; j < IC * NC; j += 256) a_s[j] = 0.f;
  __syncthreads();

  for (int it = 0; it < 3; ++it) {
    // ---- norm_q per capsule (warps 0..4) + zero hat_v ----
    if (warp < NC) {
      float s = 0.f, s2 = 0.f;
      for (int d = lane; d < DD; d += 32) {
        float x = tq[warp * DD + d];
        s += x;
        s2 += x * x;
      }
      s = warp_sum(s);
      s2 = warp_sum(s2);
      if (lane == 0) {
        float mean = s * (1.f / DD);
        float var = s2 - (float)DD * mean * mean;
        rnq[warp] = sqrtf(fmaxf(var, 0.f));
      }
    }
    for (int j = t; j < CD; j += 256) hv[j] = 0.f;
    __syncthreads();

    // ---- fused p + hat_v pass ----
    float hvp[25];
#pragma unroll
    for (int s = 0; s < 25; ++s) hvp[s] = 0.f;

    const bool notlast = (it < 2);
    for (int i = warp; i < IC; i += 8) {
      float num[NC];
#pragma unroll
      for (int c = 0; c < NC; ++c) {
        const float* mrow = mc + i * CD + c * DD;
        const float* tqc = tq + c * DD;
        float acc = 0.f;
        for (int d = lane; d < DD; d += 32) acc += mrow[d] * tqc[d];
        num[c] = warp_sum(acc);
      }
      float pv[NC], dsp[NC];
      float amax = -1e30f;
#pragma unroll
      for (int c = 0; c < NC; ++c) {
        float den = norm_m[i * NC + c] * rnq[c] + EPSF;
        pv[c] = tanhf(num[c] / den);
        amax = fmaxf(amax, a_s[i * NC + c]);
      }
      float esum = 0.f, ev[NC];
#pragma unroll
      for (int c = 0; c < NC; ++c) {
        ev[c] = expf(a_s[i * NC + c] - amax);
        esum += ev[c];
      }
      float inv = 1.f / esum;
#pragma unroll
      for (int c = 0; c < NC; ++c) dsp[c] = ev[c] * inv + pv[c];
      if (notlast && lane == 0) {
#pragma unroll
        for (int c = 0; c < NC; ++c) p_s[i * NC + c] = pv[c];
      }
      const float* hrow = hat_m + i * CD;
#pragma unroll
      for (int c = 0; c < NC; ++c) {
#pragma unroll
        for (int k = 0; k < 5; ++k) {
          int d = lane + 32 * k;
          if (d < DD) hvp[c * 5 + k] += hrow[c * DD + d] * dsp[c];
        }
      }
    }
    // per-warp partials -> shared hat_v
#pragma unroll
    for (int c = 0; c < NC; ++c) {
#pragma unroll
      for (int k = 0; k < 5; ++k) {
        int d = lane + 32 * k;
        if (d < DD) atomicAdd(&hv[c * DD + d], hvp[c * 5 + k]);
      }
    }
    __syncthreads();

    // ---- squash: v = (n2/(1+n2)) * hv / sqrt(n2+eps) per capsule ----
    if (warp < NC) {
      float s2 = 0.f;
      for (int d = lane; d < DD; d += 32) {
        float x = hv[warp * DD + d];
        s2 += x * x;
      }
      s2 = warp_sum(s2);
      float scale = s2 / ((1.f + s2) * sqrtf(s2 + EPSF));
      for (int d = lane; d < DD; d += 32) vv[warp * DD + d] = hv[warp * DD + d] * scale;
    }
    __syncthreads();

    if (it == 2) break;

    // ---- m_dot_v pass + a update ----
    for (int i = warp; i < IC; i += 8) {
      float mv[NC];
#pragma unroll
      for (int c = 0; c < NC; ++c) {
        const float* hrow = hat_m + i * CD + c * DD;
        const float* vc = vv + c * DD;
        float acc = 0.f;
        for (int d = lane; d < DD; d += 32) acc += hrow[d] * vc[d];
        mv[c] = warp_sum(acc);
      }
      if (lane == 0) {
#pragma unroll
        for (int c = 0; c < NC; ++c) a_s[i * NC + c] += p_s[i * NC + c] * mv[c];
      }
    }
    __syncthreads();
    for (int j = t; j < CD; j += 256) tq[j] = (tq[j] + vv[j]) * 0.5f;
    __syncthreads();
  }

  for (int j = t; j < CD; j += 256) out[q * CD + j] = vv[j];
}

// ---------------------------------------------------------------------------
extern "C" void kernel_launch(void* const* d_in, const int* in_sizes, int n_in,
                              void* d_out, int out_size) {
  // Identify inputs by element count (all distinct): m=98304, q=196608,
  // W=587520, b=765.
  const float *m = nullptr, *q = nullptr, *W = nullptr, *b = nullptr;
  for (int i = 0; i < n_in; ++i) {
    switch (in_sizes[i]) {
      case IC * KD: m = (const float*)d_in[i]; break;
      case NQV * KD: q = (const float*)d_in[i]; break;
      case KD * CD: W = (const float*)d_in[i]; break;
      case CD: b = (const float*)d_in[i]; break;
      default: break;
    }
  }
  float* out = (float*)d_out;

  void *p_hm, *p_mc, *p_nm, *p_hq;
  cudaGetSymbolAddress(&p_hm, g_hat_m);
  cudaGetSymbolAddress(&p_mc, g_mc);
  cudaGetSymbolAddress(&p_nm, g_norm_m);
  cudaGetSymbolAddress(&p_hq, g_hat_q);

  dim3 gm(2, (IC + 3) / 4);
  dim3 gq(2, (NQV + 3) / 4);
  gemm_kernel<<<gm, 128>>>(m, W, b, (float*)p_hm, IC);
  gemm_kernel<<<gq, 128>>>(q, W, b, (float*)p_hq, NQV);
  stats_kernel<<<(IC * NC + 7) / 8, 256>>>((const float*)p_hm, (float*)p_mc,
                                           (float*)p_nm);
  routing_kernel<<<NQV, 256>>>((const float*)p_hm, (const float*)p_mc,
                               (const float*)p_nm, (const float*)p_hq, out);
}

// round 2
// speedup vs baseline: 6.2874x; 6.2874x over previous
#include <cuda_runtime.h>
#include <math.h>

#define IC 128
#define NC 5
#define DD 153
#define DP 160      // padded capsule dim
#define CD 765
#define CDP 768     // padded row stride for GEMM outputs / Wp
#define ROWP 800    // NC*DP
#define KD 768
#define NQV 256
#define EPSF 1e-8f

__device__ __align__(16) float g_hm[IC * CDP];      // hat_m (padded stride)
__device__ __align__(16) float g_hq[NQV * CDP];     // hat_q (padded stride)
__device__ __align__(16) float g_hmT[NC * DD * IC]; // [c][d][i]
__device__ __align__(16) float g_hmP[IC * ROWP];    // [i][c][dp], zero pads
__device__ __align__(16) float g_mean[NC * IC];     // [c][i]
__device__ __align__(16) float g_norm[NC * IC];     // [c][i]
__device__ __align__(16) float g_Wp[KD * CDP];      // zero-padded W

__device__ __forceinline__ float warp_sum(float v) {
#pragma unroll
  for (int o = 16; o; o >>= 1) v += __shfl_xor_sync(0xffffffffu, v, o);
  return v;
}

// ---------------------------------------------------------------------------
// Pad W [768][765] -> Wp [768][768] (zero pad cols 765..767)
// ---------------------------------------------------------------------------
__global__ __launch_bounds__(256) void wpad_kernel(const float* __restrict__ W,
                                                   float* __restrict__ Wp) {
  int idx = blockIdx.x * 256 + threadIdx.x;
  if (idx < KD * CDP) {
    int k = idx / CDP, c = idx - k * CDP;
    Wp[idx] = (c < CD) ? W[k * CD + c] : 0.f;
  }
}

// ---------------------------------------------------------------------------
// Fused GEMM: rows 0..127 = m, 128..383 = q.  out = A @ Wp + b
// BM=32, BN=64, BK=32, 256 threads, 2x4 register tile. Grid (12,12).
// ---------------------------------------------------------------------------
#define BM 32
#define BN 64
#define BK 32

__global__ __launch_bounds__(256) void gemm_kernel(
    const float* __restrict__ Am, const float* __restrict__ Aq,
    const float* __restrict__ Wp, const float* __restrict__ bias,
    float* __restrict__ Om, float* __restrict__ Oq) {
  __shared__ float As[BK][BM + 1];
  __shared__ float Bs[BK][BN];
  const int t = threadIdx.x;
  const int row0 = blockIdx.y * BM;
  const int c0 = blockIdx.x * BN;

  const float* A;
  float* O;
  if (row0 < IC) { A = Am + row0 * KD; O = Om + row0 * CDP; }
  else           { A = Aq + (row0 - IC) * KD; O = Oq + (row0 - IC) * CDP; }

  const int ar = t >> 3, akc = (t & 7) << 2;  // A: row, k-chunk*4
  const int br = t >> 4, bc = (t & 15) << 2;  // B: k-row, col-chunk*4
  const int ty = t >> 4, tx = t & 15;

  float acc[2][4] = {};

  for (int k0 = 0; k0 < KD; k0 += BK) {
    float4 av = *(const float4*)(A + ar * KD + k0 + akc);
    As[akc + 0][ar] = av.x;
    As[akc + 1][ar] = av.y;
    As[akc + 2][ar] = av.z;
    As[akc + 3][ar] = av.w;
    *(float4*)&Bs[br][bc]      = *(const float4*)(Wp + (k0 + br) * CDP + c0 + bc);
    *(float4*)&Bs[br + 16][bc] = *(const float4*)(Wp + (k0 + br + 16) * CDP + c0 + bc);
    __syncthreads();
#pragma unroll
    for (int kk = 0; kk < BK; ++kk) {
      float a0 = As[kk][ty];
      float a1 = As[kk][ty + 16];
      float4 b = *(const float4*)&Bs[kk][tx << 2];
      acc[0][0] += a0 * b.x; acc[0][1] += a0 * b.y;
      acc[0][2] += a0 * b.z; acc[0][3] += a0 * b.w;
      acc[1][0] += a1 * b.x; acc[1][1] += a1 * b.y;
      acc[1][2] += a1 * b.z; acc[1][3] += a1 * b.w;
    }
    __syncthreads();
  }

#pragma unroll
  for (int rr = 0; rr < 2; ++rr) {
    int lr = ty + rr * 16;
#pragma unroll
    for (int j = 0; j < 4; ++j) {
      int c = c0 + (tx << 2) + j;
      if (c < CD) O[lr * CDP + c] = acc[rr][j] + bias[c];
    }
  }
}

// ---------------------------------------------------------------------------
// Stats: per (i,c) mean + centered norm; build hmT [c][d][i] and hmP [i][c][dp]
// One warp per (i,c).
// ---------------------------------------------------------------------------
__global__ __launch_bounds__(256) void stats_kernel(
    const float* __restrict__ hm, float* __restrict__ hmT,
    float* __restrict__ hmP, float* __restrict__ meanA,
    float* __restrict__ normA) {
  int g = blockIdx.x * 8 + (threadIdx.x >> 5);
  int lane = threadIdx.x & 31;
  if (g >= IC * NC) return;
  int i = g / NC, c = g - i * NC;
  const float* row = hm + i * CDP + c * DD;
  float vals[5];
  float s = 0.f, s2 = 0.f;
#pragma unroll
  for (int k = 0; k < 5; ++k) {
    int d = lane + 32 * k;
    float x = (d < DD) ? row[d] : 0.f;
    vals[k] = x;
    s += x;
    s2 += x * x;
  }
  s = warp_sum(s);
  s2 = warp_sum(s2);
  float mean = s * (1.f / DD);
  if (lane == 0) {
    meanA[c * IC + i] = mean;
    normA[c * IC + i] = sqrtf(fmaxf(s2 - DD * mean * mean, 0.f));
  }
#pragma unroll
  for (int k = 0; k < 5; ++k) {
    int d = lane + 32 * k;
    if (d < DD) hmT[(c * DD + d) * IC + i] = vals[k];
    hmP[i * ROWP + c * DP + d] = vals[k];  // d<160 always; zero pads
  }
}

// ---------------------------------------------------------------------------
// Routing: one block per query. 160 threads = 5 warps, warp w <-> capsule c=w.
// Register/layout scheme: no shfl reductions in the hot passes.
//   pass A: lane owns 4 i's (hmT LDG.128), fused num + m_dot_v dots over d.
//   i-pass: thread=i does a update, p=tanh, softmax, dsp.
//   pass B: thread owns float4 d-chunks of hv, serial over i (hmP LDG.128).
// ---------------------------------------------------------------------------
__global__ __launch_bounds__(160) void routing_kernel(
    const float* __restrict__ hmT, const float* __restrict__ hmP,
    const float* __restrict__ meanA, const float* __restrict__ normA,
    const float* __restrict__ hq, float* __restrict__ out) {
  __shared__ __align__(16) float tq_s[NC * DP];
  __shared__ __align__(16) float v_s[NC * DP];
  __shared__ __align__(16) float hv_s[NC * DP];
  __shared__ __align__(16) float num_s[NC * IC];
  __shared__ __align__(16) float mdv_s[NC * IC];
  __shared__ __align__(16) float a_s[NC * IC];
  __shared__ __align__(16) float p_s[NC * IC];
  __shared__ __align__(16) float dsp_s[NC * IC];
  __shared__ __align__(16) float norm_sm[NC * IC];
  __shared__ __align__(16) float mean_sm[NC * IC];
  __shared__ float rnq[NC], stq[NC];

  const int q = blockIdx.x;
  const int t = threadIdx.x;
  const int w = t >> 5, lane = t & 31;

  for (int j = t; j < NC * DP; j += 160) {
    int c = j / DP, d = j - c * DP;
    tq_s[j] = (d < DD) ? hq[q * CDP + c * DD + d] : 0.f;
    v_s[j] = 0.f;
  }
  for (int j = t; j < NC * IC; j += 160) {
    a_s[j] = 0.f;
    p_s[j] = 0.f;
    norm_sm[j] = normA[j];
    mean_sm[j] = meanA[j];
  }
  __syncthreads();

  for (int r = 0; r < 3; ++r) {
    // ---- small pass: tq update + sum/norm per capsule (warp w = c) ----
    {
      const int c = w;
      float s = 0.f, s2 = 0.f;
      for (int d = lane; d < DP; d += 32) {
        float x = tq_s[c * DP + d];
        if (r > 0) {
          x = (x + v_s[c * DP + d]) * 0.5f;
          tq_s[c * DP + d] = x;
        }
        s += x;
        s2 += x * x;
      }
      s = warp_sum(s);
      s2 = warp_sum(s2);
      if (lane == 0) {
        float mean = s * (1.f / DD);
        rnq[c] = sqrtf(fmaxf(s2 - DD * mean * mean, 0.f));
        stq[c] = s;
      }
    }
    __syncthreads();

    // ---- pass A: fused num + mdv dots; lane owns i in {4l..4l+3} ----
    {
      const int c = w;
      const float* base = hmT + c * DD * IC + 4 * lane;
      const float* tqc = tq_s + c * DP;
      const float* vc = v_s + c * DP;
      float4 an = {0.f, 0.f, 0.f, 0.f};
      float4 av = {0.f, 0.f, 0.f, 0.f};
#pragma unroll 3
      for (int d = 0; d < DD; ++d) {
        float4 h = *(const float4*)(base + d * IC);
        float td = tqc[d], vd = vc[d];
        an.x += h.x * td; an.y += h.y * td; an.z += h.z * td; an.w += h.w * td;
        av.x += h.x * vd; av.y += h.y * vd; av.z += h.z * vd; av.w += h.w * vd;
      }
      const int o = c * IC + 4 * lane;
      float4 mn = *(const float4*)(mean_sm + o);
      float st = stq[c];
      float4 nm;
      nm.x = an.x - mn.x * st;
      nm.y = an.y - mn.y * st;
      nm.z = an.z - mn.z * st;
      nm.w = an.w - mn.w * st;
      *(float4*)(num_s + o) = nm;
      *(float4*)(mdv_s + o) = av;
    }
    __syncthreads();

    // ---- i-pass: a update, p, softmax, dsp (thread = i) ----
    if (t < IC) {
      float a[NC], p[NC];
      float amax = -1e30f;
#pragma unroll
      for (int c = 0; c < NC; ++c) {
        int o = c * IC + t;
        float po = p_s[o];
        float av = a_s[o] + po * mdv_s[o];
        a_s[o] = av;
        a[c] = av;
        float den = norm_sm[o] * rnq[c] + EPSF;
        p[c] = tanhf(num_s[o] / den);
        p_s[o] = p[c];
        amax = fmaxf(amax, av);
      }
      float es = 0.f, e[NC];
#pragma unroll
      for (int c = 0; c < NC; ++c) {
        e[c] = expf(a[c] - amax);
        es += e[c];
      }
      float inv = 1.f / es;
#pragma unroll
      for (int c = 0; c < NC; ++c) dsp_s[c * IC + t] = e[c] * inv + p[c];
    }
    __syncthreads();

    // ---- pass B: hv[c][d4] = sum_i hmP * dsp  (thread owns float4 chunks) ----
    for (int chunk = t; chunk < NC * DP / 4; chunk += 160) {
      const int c = chunk / (DP / 4);
      const float4* src = (const float4*)hmP + chunk;
      const float* dspc = dsp_s + c * IC;
      float4 acc = {0.f, 0.f, 0.f, 0.f};
#pragma unroll 4
      for (int i = 0; i < IC; ++i) {
        float wg = dspc[i];
        float4 h = src[i * (ROWP / 4)];
        acc.x += h.x * wg; acc.y += h.y * wg;
        acc.z += h.z * wg; acc.w += h.w * wg;
      }
      ((float4*)hv_s)[chunk] = acc;
    }
    __syncthreads();

    // ---- squash (warp w = c) ----
    {
      const int c = w;
      float s2 = 0.f;
      for (int d = lane; d < DP; d += 32) {
        float x = hv_s[c * DP + d];
        s2 += x * x;
      }
      s2 = warp_sum(s2);
      float sc = s2 / ((1.f + s2) * sqrtf(s2 + EPSF));
      if (r < 2) {
        for (int d = lane; d < DP; d += 32) v_s[c * DP + d] = hv_s[c * DP + d] * sc;
      } else {
        for (int d = lane; d < DD; d += 32)
          out[q * CD + c * DD + d] = hv_s[c * DP + d] * sc;
      }
    }
    __syncthreads();
  }
}

// ---------------------------------------------------------------------------
extern "C" void kernel_launch(void* const* d_in, const int* in_sizes, int n_in,
                              void* d_out, int out_size) {
  const float *m = nullptr, *q = nullptr, *W = nullptr, *b = nullptr;
  for (int i = 0; i < n_in; ++i) {
    switch (in_sizes[i]) {
      case IC * KD: m = (const float*)d_in[i]; break;
      case NQV * KD: q = (const float*)d_in[i]; break;
      case KD * CD: W = (const float*)d_in[i]; break;
      case CD: b = (const float*)d_in[i]; break;
      default: break;
    }
  }
  float* out = (float*)d_out;

  void *p_hm, *p_hq, *p_hmT, *p_hmP, *p_mean, *p_norm, *p_wp;
  cudaGetSymbolAddress(&p_hm, g_hm);
  cudaGetSymbolAddress(&p_hq, g_hq);
  cudaGetSymbolAddress(&p_hmT, g_hmT);
  cudaGetSymbolAddress(&p_hmP, g_hmP);
  cudaGetSymbolAddress(&p_mean, g_mean);
  cudaGetSymbolAddress(&p_norm, g_norm);
  cudaGetSymbolAddress(&p_wp, g_Wp);

  wpad_kernel<<<(KD * CDP + 255) / 256, 256>>>(W, (float*)p_wp);

  dim3 gg(CDP / BN, (IC + NQV) / BM);  // (12, 12)
  gemm_kernel<<<gg, 256>>>(m, q, (const float*)p_wp, b, (float*)p_hm,
                           (float*)p_hq);

  stats_kernel<<<(IC * NC + 7) / 8, 256>>>((const float*)p_hm, (float*)p_hmT,
                                           (float*)p_hmP, (float*)p_mean,
                                           (float*)p_norm);

  routing_kernel<<<NQV, 160>>>((const float*)p_hmT, (const float*)p_hmP,
                               (const float*)p_mean, (const float*)p_norm,
                               (const float*)p_hq, out);
}